// round 1
// baseline (speedup 1.0000x reference)
#include <cuda_runtime.h>
#include <math.h>

#define B_TOTAL 500000
#define F 100
#define NT 10
#define C 10
#define H 7

// Shared layout sizes
#define WT_SZ   (NT*H*C)   // 700
#define HBT_SZ  (NT*H)     // 70
#define VBT_SZ  (NT*C)     // 100
#define WH_SZ   (H*NT)     // 70
#define HBH_SZ  (H)        // 7
#define VBH_SZ  (NT)       // 10
#define CL_SZ   (NT*C)     // 100

__global__ __launch_bounds__(256)
void kitnet_kernel(const float* __restrict__ x,
                   const float* __restrict__ Wt,
                   const float* __restrict__ hbias_t,
                   const float* __restrict__ vbias_t,
                   const float* __restrict__ Wh,
                   const float* __restrict__ hbias_h,
                   const float* __restrict__ vbias_h,
                   const int*   __restrict__ clusters,
                   float* __restrict__ out_head,   // [B, NT]
                   float* __restrict__ out_tails)  // [B, NT]
{
    __shared__ float sWt[WT_SZ];
    __shared__ float sHbt[HBT_SZ];
    __shared__ float sVbt[VBT_SZ];
    __shared__ float sWh[WH_SZ];
    __shared__ float sHbh[HBH_SZ];
    __shared__ float sVbh[VBH_SZ];
    __shared__ int   sCl[CL_SZ];

    const int tid = threadIdx.x;
    // Cooperative staging of all small parameters.
    for (int i = tid; i < WT_SZ;  i += blockDim.x) sWt[i]  = Wt[i];
    for (int i = tid; i < HBT_SZ; i += blockDim.x) sHbt[i] = hbias_t[i];
    for (int i = tid; i < VBT_SZ; i += blockDim.x) sVbt[i] = vbias_t[i];
    for (int i = tid; i < WH_SZ;  i += blockDim.x) sWh[i]  = Wh[i];
    for (int i = tid; i < HBH_SZ; i += blockDim.x) sHbh[i] = hbias_h[i];
    for (int i = tid; i < VBH_SZ; i += blockDim.x) sVbh[i] = vbias_h[i];
    for (int i = tid; i < CL_SZ;  i += blockDim.x) sCl[i]  = clusters[i];
    __syncthreads();

    const int b = blockIdx.x * blockDim.x + tid;
    if (b >= B_TOTAL) return;

    const float* xrow = x + (long long)b * F;

    float tails[NT];

    #pragma unroll
    for (int t = 0; t < NT; t++) {
        // Gather this tree's cluster of inputs.
        float xc[C];
        #pragma unroll
        for (int c = 0; c < C; c++) {
            xc[c] = __ldg(xrow + sCl[t * C + c]);
        }

        // z[h] = hbias_t[t,h] + sum_c xc[c] * Wt[t,h,c]
        float z[H];
        #pragma unroll
        for (int h = 0; h < H; h++) {
            float acc = sHbt[t * H + h];
            const float* w = &sWt[(t * H + h) * C];
            #pragma unroll
            for (int c = 0; c < C; c++) acc = fmaf(xc[c], w[c], acc);
            z[h] = acc;
        }

        // out[c] = vbias_t[t,c] + sum_h z[h] * Wt[t,h,c]; accumulate SSE
        float sse = 0.0f;
        #pragma unroll
        for (int c = 0; c < C; c++) {
            float o = sVbt[t * C + c];
            #pragma unroll
            for (int h = 0; h < H; h++) o = fmaf(z[h], sWt[(t * H + h) * C + c], o);
            float d = o - xc[c];
            sse = fmaf(d, d, sse);
        }

        float rmse = sqrtf(sse * (1.0f / (float)C));
        tails[t] = logf(rmse);
    }

    // Head layer: zh = tails @ Wh^T + hbias_h ; head_out = zh @ Wh + vbias_h
    float zh[H];
    #pragma unroll
    for (int h = 0; h < H; h++) {
        float acc = sHbh[h];
        #pragma unroll
        for (int t = 0; t < NT; t++) acc = fmaf(tails[t], sWh[h * NT + t], acc);
        zh[h] = acc;
    }

    float ho[NT];
    #pragma unroll
    for (int t = 0; t < NT; t++) {
        float acc = sVbh[t];
        #pragma unroll
        for (int h = 0; h < H; h++) acc = fmaf(zh[h], sWh[h * NT + t], acc);
        ho[t] = acc;
    }

    // Write outputs: head_out then tails, each [B, NT], via float2 stores
    // (b*NT*4 bytes = 40b, 8-byte aligned for all b).
    float2* hdst = reinterpret_cast<float2*>(out_head + (long long)b * NT);
    float2* tdst = reinterpret_cast<float2*>(out_tails + (long long)b * NT);
    #pragma unroll
    for (int i = 0; i < NT / 2; i++) {
        hdst[i] = make_float2(ho[2 * i], ho[2 * i + 1]);
        tdst[i] = make_float2(tails[2 * i], tails[2 * i + 1]);
    }
}

extern "C" void kernel_launch(void* const* d_in, const int* in_sizes, int n_in,
                              void* d_out, int out_size) {
    const float* x       = (const float*)d_in[0];
    const float* Wt      = (const float*)d_in[1];
    const float* hbias_t = (const float*)d_in[2];
    const float* vbias_t = (const float*)d_in[3];
    const float* Wh      = (const float*)d_in[4];
    const float* hbias_h = (const float*)d_in[5];
    const float* vbias_h = (const float*)d_in[6];
    const int*   clusters= (const int*)d_in[7];

    float* out = (float*)d_out;
    float* out_head  = out;                       // [B, NT]
    float* out_tails = out + (long long)B_TOTAL * NT; // [B, NT]

    const int threads = 256;
    const int blocks = (B_TOTAL + threads - 1) / threads;
    kitnet_kernel<<<blocks, threads>>>(x, Wt, hbias_t, vbias_t, Wh,
                                       hbias_h, vbias_h, clusters,
                                       out_head, out_tails);
}